// round 1
// baseline (speedup 1.0000x reference)
#include <cuda_runtime.h>
#include <cuda_bf16.h>

// Problem constants (fixed by the reference)
#define N_NODES 100000
#define N_EDGES 1600000
#define D       64

// Scratch (allocation-free rule: __device__ globals)
__device__ float g_agg[(size_t)N_NODES * D];   // 25.6 MB
__device__ float g_cnt[N_NODES];

// ---------------------------------------------------------------------------
// Kernel 1: zero the aggregation scratch
// ---------------------------------------------------------------------------
__global__ void zero_kernel() {
    int gid    = blockIdx.x * blockDim.x + threadIdx.x;
    int stride = gridDim.x * blockDim.x;
    float4 z = make_float4(0.f, 0.f, 0.f, 0.f);
    float4* a4 = reinterpret_cast<float4*>(g_agg);
    const int total4 = N_NODES * D / 4;
    for (int k = gid; k < total4; k += stride) a4[k] = z;
    for (int k = gid; k < N_NODES; k += stride) g_cnt[k] = 0.f;
}

// ---------------------------------------------------------------------------
// Kernel 2: edge scatter  agg[src] += x[tgt];  cnt[src] += 1
// 16 threads per edge, one float4 vector-RED per thread (no return value).
// ---------------------------------------------------------------------------
__device__ __forceinline__ void red_add_v4(float* addr, float4 v) {
    asm volatile("red.global.add.v4.f32 [%0], {%1, %2, %3, %4};"
                 :: "l"(addr), "f"(v.x), "f"(v.y), "f"(v.z), "f"(v.w)
                 : "memory");
}
__device__ __forceinline__ void red_add_f32(float* addr, float v) {
    asm volatile("red.global.add.f32 [%0], %1;"
                 :: "l"(addr), "f"(v) : "memory");
}

__global__ void scatter_kernel(const float* __restrict__ x,
                               const int*   __restrict__ edge_index) {
    long gid = (long)blockIdx.x * blockDim.x + threadIdx.x;
    int  e    = (int)(gid >> 4);   // 16 threads per edge
    int  part = (int)(gid & 15);   // which float4 of the 64-float row
    if (e >= N_EDGES) return;

    int s = edge_index[e];            // src
    int t = edge_index[N_EDGES + e];  // tgt

    const float4* x4 = reinterpret_cast<const float4*>(x);
    float4 v = x4[(long)t * (D / 4) + part];

    red_add_v4(&g_agg[(long)s * D + part * 4], v);
    if (part == 0) red_add_f32(&g_cnt[s], 1.0f);
}

// ---------------------------------------------------------------------------
// Kernel 3: out[i,:] = (agg[i,:] / (cnt[i]+1e-6)) @ W + b
// W staged in smem; 64 fp32 accumulators per thread; broadcast LDS.128.
// ---------------------------------------------------------------------------
__global__ void norm_gemm_kernel(const float* __restrict__ W,
                                 const float* __restrict__ b,
                                 float*       __restrict__ out) {
    __shared__ float Ws[D * D];   // 16 KB
    __shared__ float bs[D];

    for (int k = threadIdx.x; k < D * D; k += blockDim.x) Ws[k] = W[k];
    if (threadIdx.x < D) bs[threadIdx.x] = b[threadIdx.x];
    __syncthreads();

    int i = blockIdx.x * blockDim.x + threadIdx.x;
    if (i >= N_NODES) return;

    float scale = 1.0f / (g_cnt[i] + 1e-6f);

    float4 acc[D / 4];
    const float4* b4 = reinterpret_cast<const float4*>(bs);
#pragma unroll
    for (int j = 0; j < D / 4; j++) acc[j] = b4[j];

    const float4* a4 = reinterpret_cast<const float4*>(g_agg + (long)i * D);
    const float4* W4 = reinterpret_cast<const float4*>(Ws);

#pragma unroll
    for (int kk = 0; kk < D / 4; kk++) {
        float4 r = a4[kk];
        float rs[4] = { r.x * scale, r.y * scale, r.z * scale, r.w * scale };
#pragma unroll
        for (int c = 0; c < 4; c++) {
            int k = kk * 4 + c;
#pragma unroll
            for (int j = 0; j < D / 4; j++) {
                float4 w = W4[k * (D / 4) + j];
                acc[j].x += rs[c] * w.x;
                acc[j].y += rs[c] * w.y;
                acc[j].z += rs[c] * w.z;
                acc[j].w += rs[c] * w.w;
            }
        }
    }

    float4* o4 = reinterpret_cast<float4*>(out + (long)i * D);
#pragma unroll
    for (int j = 0; j < D / 4; j++) o4[j] = acc[j];
}

// ---------------------------------------------------------------------------
// Launch
// ---------------------------------------------------------------------------
extern "C" void kernel_launch(void* const* d_in, const int* in_sizes, int n_in,
                              void* d_out, int out_size) {
    const float* x  = (const float*)d_in[0];   // [N, 64]
    const int*   ei = (const int*)  d_in[1];   // [2, E]
    const float* W  = (const float*)d_in[2];   // [64, 64]
    const float* b  = (const float*)d_in[3];   // [64]
    float* out = (float*)d_out;                // [N, 64]

    (void)in_sizes; (void)n_in; (void)out_size;

    zero_kernel<<<2048, 256>>>();

    // 16 threads per edge
    long scatter_threads = (long)N_EDGES * 16;
    int  scatter_blocks  = (int)((scatter_threads + 255) / 256);
    scatter_kernel<<<scatter_blocks, 256>>>(x, ei);

    int gemm_blocks = (N_NODES + 255) / 256;
    norm_gemm_kernel<<<gemm_blocks, 256>>>(W, b, out);
}